// round 14
// baseline (speedup 1.0000x reference)
#include <cuda_runtime.h>
#include <math.h>
#include <stdint.h>

#define HN    512
#define NST   64
#define LL    2048
#define LF    4096
#define BT    8
#define NT    256
#define NK    128

// ---------------- scratch ----------------
__device__ float2 g_AT[HN * LL];        // at_roots (h, l)
__device__ float2 g_KF[HN * LF];        // kernel spectrum / 4096
__device__ float  g_UT[BT * HN * LL];   // u transposed (b,h,l)
__device__ float  g_YT[BT * HN * LL];   // y transposed (b,h,l)
__device__ float2 g_TW[2048];           // W_4096^k

// ---------------- helpers ----------------
__device__ __forceinline__ float2 cadd(float2 a, float2 b) { return make_float2(a.x + b.x, a.y + b.y); }
__device__ __forceinline__ float2 csub(float2 a, float2 b) { return make_float2(a.x - b.x, a.y - b.y); }
__device__ __forceinline__ float2 cmulf(float2 a, float2 b) {
    return make_float2(fmaf(a.x, b.x, -(a.y * b.y)), fmaf(a.x, b.y, a.y * b.x));
}

// f32x2 packed math (cauchy)
__device__ __forceinline__ unsigned long long pk2(float a, float b) {
    unsigned long long r; asm("mov.b64 %0, {%1, %2};" : "=l"(r) : "f"(a), "f"(b)); return r;
}
__device__ __forceinline__ void up2(unsigned long long v, float& a, float& b) {
    asm("mov.b64 {%0, %1}, %2;" : "=f"(a), "=f"(b) : "l"(v));
}
__device__ __forceinline__ unsigned long long f2fma(unsigned long long a, unsigned long long b, unsigned long long c) {
    unsigned long long d; asm("fma.rn.f32x2 %0, %1, %2, %3;" : "=l"(d) : "l"(a), "l"(b), "l"(c)); return d;
}
__device__ __forceinline__ unsigned long long f2add(unsigned long long a, unsigned long long b) {
    unsigned long long d; asm("add.rn.f32x2 %0, %1, %2;" : "=l"(d) : "l"(a), "l"(b)); return d;
}
__device__ __forceinline__ unsigned long long f2mul(unsigned long long a, unsigned long long b) {
    unsigned long long d; asm("mul.rn.f32x2 %0, %1, %2;" : "=l"(d) : "l"(a), "l"(b)); return d;
}
__device__ __forceinline__ float rcpa(float x) {
    float r; asm("rcp.approx.f32 %0, %1;" : "=f"(r) : "f"(x)); return r;
}
__device__ __forceinline__ float hsum(unsigned long long v) {
    float a, b; up2(v, a, b); return a + b;
}

// ---------------- register butterflies ----------------
template <int DIR>
__device__ __forceinline__ void bfly8(const float2 v[8], float2 X[8]) {
    float2 s0 = cadd(v[0], v[4]), d0 = csub(v[0], v[4]);
    float2 s1 = cadd(v[2], v[6]), d1 = csub(v[2], v[6]);
    float2 E0 = cadd(s0, s1), E2 = csub(s0, s1);
    float2 id1 = (DIR < 0) ? make_float2(d1.y, -d1.x) : make_float2(-d1.y, d1.x);
    float2 E1 = cadd(d0, id1), E3 = csub(d0, id1);
    float2 t0 = cadd(v[1], v[5]), u0 = csub(v[1], v[5]);
    float2 t1 = cadd(v[3], v[7]), u1 = csub(v[3], v[7]);
    float2 O0 = cadd(t0, t1), O2 = csub(t0, t1);
    float2 iu1 = (DIR < 0) ? make_float2(u1.y, -u1.x) : make_float2(-u1.y, u1.x);
    float2 O1 = cadd(u0, iu1), O3 = csub(u0, iu1);
    const float c = 0.70710678118654752440f;
    float2 w1O1, w2O2, w3O3;
    if (DIR < 0) {
        w1O1 = make_float2(c * (O1.x + O1.y), c * (O1.y - O1.x));
        w2O2 = make_float2(O2.y, -O2.x);
        w3O3 = make_float2(c * (O3.y - O3.x), -c * (O3.x + O3.y));
    } else {
        w1O1 = make_float2(c * (O1.x - O1.y), c * (O1.x + O1.y));
        w2O2 = make_float2(-O2.y, O2.x);
        w3O3 = make_float2(-c * (O3.x + O3.y), c * (O3.x - O3.y));
    }
    X[0] = cadd(E0, O0);   X[4] = csub(E0, O0);
    X[1] = cadd(E1, w1O1); X[5] = csub(E1, w1O1);
    X[2] = cadd(E2, w2O2); X[6] = csub(E2, w2O2);
    X[3] = cadd(E3, w3O3); X[7] = csub(E3, w3O3);
}

template <int DIR>
__device__ __forceinline__ void fft16(float2 v[16]) {
    const float C1 = 0.9238795325112867f;
    const float S1 = 0.3826834323650898f;
    const float R2 = 0.7071067811865476f;
    const float sg = (DIR < 0) ? -1.0f : 1.0f;
    float2 u[16];
#pragma unroll
    for (int j = 0; j < 4; j++) {
        float2 a = v[j], b = v[j + 4], c = v[j + 8], d = v[j + 12];
        float2 A0 = cadd(a, c), A1 = csub(a, c);
        float2 B0 = cadd(b, d), B1 = csub(b, d);
        float2 iB1 = (DIR < 0) ? make_float2(B1.y, -B1.x) : make_float2(-B1.y, B1.x);
        u[j]      = cadd(A0, B0);
        u[4 + j]  = cadd(A1, iB1);
        u[8 + j]  = csub(A0, B0);
        u[12 + j] = csub(A1, iB1);
    }
    u[5]  = cmulf(u[5],  make_float2(C1,  sg * S1));
    u[6]  = cmulf(u[6],  make_float2(R2,  sg * R2));
    u[7]  = cmulf(u[7],  make_float2(S1,  sg * C1));
    u[9]  = cmulf(u[9],  make_float2(R2,  sg * R2));
    u[10] = (DIR < 0) ? make_float2(u[10].y, -u[10].x) : make_float2(-u[10].y, u[10].x);
    u[11] = cmulf(u[11], make_float2(-R2, sg * R2));
    u[13] = cmulf(u[13], make_float2(S1,  sg * C1));
    u[14] = cmulf(u[14], make_float2(-R2, sg * R2));
    u[15] = cmulf(u[15], make_float2(-C1, -sg * S1));
#pragma unroll
    for (int k = 0; k < 4; k++) {
        float2 a = u[k * 4 + 0], b = u[k * 4 + 1], c = u[k * 4 + 2], d = u[k * 4 + 3];
        float2 A0 = cadd(a, c), A1 = csub(a, c);
        float2 B0 = cadd(b, d), B1 = csub(b, d);
        float2 iB1 = (DIR < 0) ? make_float2(B1.y, -B1.x) : make_float2(-B1.y, B1.x);
        v[k]      = cadd(A0, B0);
        v[k + 4]  = cadd(A1, iB1);
        v[k + 8]  = csub(A0, B0);
        v[k + 12] = csub(A1, iB1);
    }
}

// tree-factored twiddle application: v[k] *= w1^k (conj if CONJ). Depth ~4 vs 14.
template <int CONJ>
__device__ __forceinline__ void twapply(float2 v[16], float2 w1) {
    if (CONJ) w1.y = -w1.y;
    float2 w2  = cmulf(w1, w1);
    float2 w4  = cmulf(w2, w2);
    float2 w8  = cmulf(w4, w4);
    float2 w12 = cmulf(w8, w4);
    float2 w3  = cmulf(w2, w1);
    v[1]  = cmulf(v[1],  w1);
    v[2]  = cmulf(v[2],  w2);
    v[3]  = cmulf(v[3],  w3);
    v[4]  = cmulf(v[4],  w4);
    v[5]  = cmulf(v[5],  cmulf(w4, w1));
    v[6]  = cmulf(v[6],  cmulf(w4, w2));
    v[7]  = cmulf(v[7],  cmulf(w4, w3));
    v[8]  = cmulf(v[8],  w8);
    v[9]  = cmulf(v[9],  cmulf(w8, w1));
    v[10] = cmulf(v[10], cmulf(w8, w2));
    v[11] = cmulf(v[11], cmulf(w8, w3));
    v[12] = cmulf(v[12], w12);
    v[13] = cmulf(v[13], cmulf(w12, w1));
    v[14] = cmulf(v[14], cmulf(w12, w2));
    v[15] = cmulf(v[15], cmulf(w12, w3));
}

// ================= K_pre: fused twiddle + transpose_in(64x64) + cauchy =================
// Identity: g = (2/step)*(1-Omega)/(1+Omega) = i*(2/step)*tan(pi*l/L)  (purely imaginary),
//           c_scale = 2/(1+Omega) = 1 + i*tan(pi*l/L).

__device__ __forceinline__ void cauchy_body(
        int i, int t, char* smraw,
        const float* __restrict__ Lre, const float* __restrict__ Lim,
        const float* __restrict__ P, const float* __restrict__ B,
        const float* __restrict__ C, const float* __restrict__ logstep) {
    ulonglong2* s_q01 = (ulonglong2*)smraw;                    // {lre^2 pair, -lim pair}
    ulonglong2* s_q23 = s_q01 + 32;                            // {w00r, w00i}
    ulonglong2* s_q45 = s_q23 + 32;                            // {w01r, w01i}
    ulonglong2* s_q67 = s_q45 + 32;                            // {w10r, w10i}
    unsigned long long* s_q8 = (unsigned long long*)(s_q67 + 32);  // {w11r}
    unsigned long long* s_qn = s_q8 + 32;                      // {-lre pair}
    int h = i >> 3;
    int bx = i & 7;
    if (t < 32) {
        float lr[2], li[2], w00r[2], w00i[2], w01r[2], w01i[2], w10r[2], w10i[2], w11r[2];
#pragma unroll
        for (int k = 0; k < 2; k++) {
            int idx = h * NST + 2 * t + k;
            lr[k] = fminf(Lre[idx], -1e-4f);
            li[k] = Lim[idx];
            float pr = P[idx * 2], pi = P[idx * 2 + 1];
            float br = B[idx * 2], bi = B[idx * 2 + 1];
            float cr = C[idx * 2], ci = C[idx * 2 + 1];
            w00r[k] = cr * br + ci * bi;  w00i[k] = cr * bi - ci * br;
            w01r[k] = cr * pr + ci * pi;  w01i[k] = cr * pi - ci * pr;
            w10r[k] = pr * br + pi * bi;  w10i[k] = pr * bi - pi * br;
            w11r[k] = pr * pr + pi * pi;
        }
        s_q01[t] = make_ulonglong2(pk2(lr[0] * lr[0], lr[1] * lr[1]), pk2(-li[0], -li[1]));
        s_q23[t] = make_ulonglong2(pk2(w00r[0], w00r[1]), pk2(w00i[0], w00i[1]));
        s_q45[t] = make_ulonglong2(pk2(w01r[0], w01r[1]), pk2(w01i[0], w01i[1]));
        s_q67[t] = make_ulonglong2(pk2(w10r[0], w10r[1]), pk2(w10i[0], w10i[1]));
        s_q8[t]  = pk2(w11r[0], w11r[1]);
        s_qn[t]  = pk2(-lr[0], -lr[1]);
    }
    __syncthreads();

    int l = bx * NT + t;
    float ts = 2.0f * expf(-logstep[h]);
    float phi = (float)l * (3.14159265358979323846f / (float)LL);   // pi*l/L
    float sp, cp;
    sincosf(phi, &sp, &cp);
    float tn = __fdividef(sp, cp);       // tan(pi*l/L); huge-finite at l=1024, self-cancelling
    float gi = ts * tn;

    unsigned long long gi2 = pk2(gi, gi);
    unsigned long long S0 = 0, S1 = 0, S2 = 0, S3 = 0, S4 = 0, S5 = 0, S6 = 0;
    unsigned long long S7 = 0, S8 = 0, S9 = 0, S10 = 0, S11 = 0, S12 = 0, S13 = 0;
#pragma unroll 8
    for (int j = 0; j < 32; j++) {
        ulonglong2 q01 = s_q01[j];
        unsigned long long di = f2add(gi2, q01.y);             // gi - lim
        unsigned long long mag = f2fma(di, di, q01.x);         // di^2 + lre^2
        float m0, m1; up2(mag, m0, m1);
        unsigned long long inv = pk2(rcpa(m0), rcpa(m1));
        unsigned long long rr  = f2mul(s_qn[j], inv);          // (-lre)*inv
        unsigned long long nri = f2mul(di, inv);               // = -ri
        ulonglong2 q23 = s_q23[j];
        S0 = f2fma(q23.x, rr, S0);  S1 = f2fma(q23.y, nri, S1);
        S2 = f2fma(q23.y, rr, S2);  S3 = f2fma(q23.x, nri, S3);
        ulonglong2 q45 = s_q45[j];
        S4 = f2fma(q45.x, rr, S4);  S5 = f2fma(q45.y, nri, S5);
        S6 = f2fma(q45.y, rr, S6);  S7 = f2fma(q45.x, nri, S7);
        ulonglong2 q67 = s_q67[j];
        S8 = f2fma(q67.x, rr, S8);   S9 = f2fma(q67.y, nri, S9);
        S10 = f2fma(q67.y, rr, S10); S11 = f2fma(q67.x, nri, S11);
        unsigned long long q8 = s_q8[j];
        S12 = f2fma(q8, rr, S12);    S13 = f2fma(q8, nri, S13);
    }
    float k00r = hsum(S0) + hsum(S1),  k00i = hsum(S2) - hsum(S3);
    float k01r = hsum(S4) + hsum(S5),  k01i = hsum(S6) - hsum(S7);
    float k10r = hsum(S8) + hsum(S9),  k10i = hsum(S10) - hsum(S11);
    float k11r = hsum(S12),            k11i = -hsum(S13);

    float denr = 1.0f + k11r, deni = k11i;
    float invd = 1.0f / (denr * denr + deni * deni);
    float qr = k01r * k10r - k01i * k10i;
    float qi = k01r * k10i + k01i * k10r;
    float fr = (qr * denr + qi * deni) * invd;
    float fi = (qi * denr - qr * deni) * invd;
    float ar_ = k00r - fr, ai_ = k00i - fi;
    // at = (1 + i*tn) * (ar_ + i*ai_)
    g_AT[h * LL + l] = make_float2(fmaf(-tn, ai_, ar_), fmaf(tn, ar_, ai_));
}

// 64x64 transpose-in tile: j in [0, 2048); u (b,l,h) -> g_UT (b,h,l)
__device__ __forceinline__ void transpose_in_body(int j, int t, char* smraw,
                                                  const float* __restrict__ u) {
    float (*tile)[65] = (float (*)[65])smraw;
    int x = j & 7, y = (j >> 3) & 31, b = j >> 8;   // 8 h-tiles, 32 l-tiles per batch
    int h0 = x * 64, l0 = y * 64;
    int tx = t & 31, ty = t >> 5;                    // 32 x 8
    const float* up = u + (size_t)b * LL * HN;
#pragma unroll
    for (int k = 0; k < 64; k += 8) {
        tile[ty + k][tx]      = up[(size_t)(l0 + ty + k) * HN + h0 + tx];
        tile[ty + k][tx + 32] = up[(size_t)(l0 + ty + k) * HN + h0 + tx + 32];
    }
    __syncthreads();
    float* o = g_UT + (size_t)b * HN * LL;
#pragma unroll
    for (int k = 0; k < 64; k += 8) {
        o[(size_t)(h0 + ty + k) * LL + l0 + tx]      = tile[tx][ty + k];
        o[(size_t)(h0 + ty + k) * LL + l0 + tx + 32] = tile[tx + 32][ty + k];
    }
}

__global__ void __launch_bounds__(NT, 4) k_pre(
        const float* __restrict__ u,
        const float* __restrict__ Lre, const float* __restrict__ Lim,
        const float* __restrict__ P, const float* __restrict__ B,
        const float* __restrict__ C, const float* __restrict__ logstep) {
    __shared__ __align__(16) char smraw[64 * 65 * 4];
    int t = threadIdx.x;
    int bid = blockIdx.x;
    if (bid == 0) {
#pragma unroll
        for (int k = t; k < 2048; k += NT) {
            double s, c;
            sincospi(-2.0 * (double)k / 4096.0, &s, &c);
            g_TW[k] = make_float2((float)c, (float)s);
        }
        return;
    }
    int i = bid - 1;                 // [0, 6144): 2 cauchy : 1 tin
    int g = i / 3, r = i - 3 * g;    // g in [0, 2048)
    if (r < 2) cauchy_body(2 * g + r, t, smraw, Lre, Lim, P, B, C, logstep);
    else       transpose_in_body(g, t, smraw, u);
}

// ---------------- K2: kernel spectrum, register radix-16 (round-5 proven) ----------------
#define P1 136
#define P2 258

__global__ void __launch_bounds__(NK) k_kernelfft() {
    __shared__ float2 S0[16 * P1];
    __shared__ float2 S1[16 * P1];
    int h = blockIdx.x, t = threadIdx.x;
    const float2* ath = g_AT + (size_t)h * LL;
    float2* kfh = g_KF + (size_t)h * LF;
    const float s2 = 1.0f / 2048.0f, s4 = 1.0f / 4096.0f;
    float2 v[16];

#pragma unroll
    for (int a = 0; a < 16; a++) {
        int n = a * NK + t;
        float2 x = ath[n];
        float2 m = ath[(2048 - n) & 2047];
        float2 ats = make_float2(0.5f * (x.x + m.x), 0.5f * (x.y - m.y));
        v[a] = ats;
        kfh[2 * n] = make_float2(ats.x * s4, ats.y * s4);
    }
    fft16<+1>(v);
    twapply<1>(v, g_TW[2 * t]);
#pragma unroll
    for (int k1 = 0; k1 < 16; k1++) S0[k1 * P1 + t] = v[k1];
    __syncthreads();

    int k1t = t >> 3, t2 = t & 7;
#pragma unroll
    for (int a2 = 0; a2 < 16; a2++) v[a2] = S0[k1t * P1 + a2 * 8 + t2];
    fft16<+1>(v);
    twapply<1>(v, g_TW[32 * t2]);
#pragma unroll
    for (int k2 = 0; k2 < 16; k2++) S1[t2 * P2 + k2 * 16 + k1t] = v[k2];
    __syncthreads();

#pragma unroll
    for (int e = 0; e < 2; e++) {
        int pr = t + NK * e;
        int k1 = pr & 15, k2 = pr >> 4;
        float2 w[8], X[8];
#pragma unroll
        for (int s = 0; s < 8; s++) w[s] = S1[s * P2 + k2 * 16 + k1];
        bfly8<+1>(w, X);
#pragma unroll
        for (int k3 = 0; k3 < 8; k3++) {
            int n = k1 + 16 * k2 + 256 * k3;
            float kr = X[k3].x * s2;
            float2 tw = g_TW[n];
            S0[n] = make_float2(kr * tw.x, kr * tw.y);
        }
    }
    __syncthreads();

#pragma unroll
    for (int a = 0; a < 16; a++) v[a] = S0[a * NK + t];
    fft16<-1>(v);
    twapply<0>(v, g_TW[2 * t]);
#pragma unroll
    for (int k1 = 0; k1 < 16; k1++) S1[k1 * P1 + t] = v[k1];
    __syncthreads();

#pragma unroll
    for (int a2 = 0; a2 < 16; a2++) v[a2] = S1[k1t * P1 + a2 * 8 + t2];
    fft16<-1>(v);
    twapply<0>(v, g_TW[32 * t2]);
#pragma unroll
    for (int k2 = 0; k2 < 16; k2++) S0[t2 * P2 + k2 * 16 + k1t] = v[k2];
    __syncthreads();

#pragma unroll
    for (int e = 0; e < 2; e++) {
        int pr = t + NK * e;
        int k1 = pr & 15, k2 = pr >> 4;
        float2 w[8], X[8];
#pragma unroll
        for (int s = 0; s < 8; s++) w[s] = S0[s * P2 + k2 * 16 + k1];
        bfly8<-1>(w, X);
#pragma unroll
        for (int k3 = 0; k3 < 8; k3++) {
            int j = k1 + 16 * k2 + 256 * k3;
            kfh[2 * j + 1] = make_float2(X[k3].x * s4, X[k3].y * s4);
        }
    }
}

// ================= conv: register radix-16, natural-order (round-8 proven) =================
#define PAD_ROW 257
#define P2C     273

__global__ void __launch_bounds__(NT) k_conv(const float* __restrict__ D) {
    extern __shared__ float2 S[];       // S0[4112] | S1[4368]
    float2* S0 = S;
    float2* S1 = S + 4112;
    int blk = blockIdx.x;
    int h = blk & (HN - 1);
    int bp = blk >> 9;
    int t = threadIdx.x;
    const float* u0 = g_UT + ((size_t)(2 * bp) * HN + h) * LL;
    const float* u1 = g_UT + ((size_t)(2 * bp + 1) * HN + h) * LL;

    int c = t & 15, k1r = t >> 4;
    int sj = 17 * c + k1r;             // slot of G2(k1=t&15, k2=t>>4)
    float2 wA = g_TW[t];               // W4096^t
    float2 wB = g_TW[c << 4];          // W256^c

    float2 v[16];
    // ---- forward ----
#pragma unroll
    for (int a = 0; a < 8; a++) v[a] = make_float2(u0[a * 256 + t], u1[a * 256 + t]);
#pragma unroll
    for (int a = 8; a < 16; a++) v[a] = make_float2(0.0f, 0.0f);
    fft16<-1>(v);
    twapply<0>(v, wA);
#pragma unroll
    for (int k1 = 0; k1 < 16; k1++) S0[k1 * PAD_ROW + t] = v[k1];
    __syncthreads();
#pragma unroll
    for (int b = 0; b < 16; b++) v[b] = S0[k1r * PAD_ROW + b * 16 + c];
    fft16<-1>(v);
    twapply<0>(v, wB);
#pragma unroll
    for (int k2 = 0; k2 < 16; k2++) S1[c * P2C + 17 * k1r + k2] = v[k2];
    __syncthreads();
#pragma unroll
    for (int cc = 0; cc < 16; cc++) v[cc] = S1[cc * P2C + sj];
    fft16<-1>(v);
    // thread t holds X[t + 256*k3] — natural order

    // ---- pointwise * KF/4096 (coalesced) ----
    const float2* kf = g_KF + (size_t)h * LF;
#pragma unroll
    for (int k3 = 0; k3 < 16; k3++) v[k3] = cmulf(v[k3], __ldg(&kf[(k3 << 8) + t]));

    // ---- inverse: mirror of forward, conj twiddles ----
    fft16<+1>(v);
    twapply<1>(v, wA);
#pragma unroll
    for (int j1 = 0; j1 < 16; j1++) S0[j1 * PAD_ROW + t] = v[j1];
    __syncthreads();
#pragma unroll
    for (int b = 0; b < 16; b++) v[b] = S0[k1r * PAD_ROW + b * 16 + c];
    fft16<+1>(v);
    twapply<1>(v, wB);
#pragma unroll
    for (int j2 = 0; j2 < 16; j2++) S1[c * P2C + 17 * k1r + j2] = v[j2];
    __syncthreads();
#pragma unroll
    for (int cc = 0; cc < 16; cc++) v[cc] = S1[cc * P2C + sj];
    fft16<+1>(v);
    float dv = D[h];
    float* y0 = g_YT + ((size_t)(2 * bp) * HN + h) * LL;
    float* y1 = g_YT + ((size_t)(2 * bp + 1) * HN + h) * LL;
#pragma unroll
    for (int j3 = 0; j3 < 8; j3++) {
        int n = t + (j3 << 8);
        y0[n] = fmaf(dv, u0[n], v[j3].x);
        y1[n] = fmaf(dv, u1[n], v[j3].y);
    }
}

// ---------------- K5: transpose y (b,h,l) -> out (b,l,h), 64x64 tiles ----------------
__global__ void k_transpose_out(float* __restrict__ out) {
    __shared__ float tile[64][65];
    int b = blockIdx.z;
    int l0 = blockIdx.x * 64, h0 = blockIdx.y * 64;
    int tx = threadIdx.x, ty = threadIdx.y;
    const float* yp = g_YT + (size_t)b * HN * LL;
#pragma unroll
    for (int k = 0; k < 64; k += 8) {
        tile[ty + k][tx]      = yp[(size_t)(h0 + ty + k) * LL + l0 + tx];
        tile[ty + k][tx + 32] = yp[(size_t)(h0 + ty + k) * LL + l0 + tx + 32];
    }
    __syncthreads();
    float* op = out + (size_t)b * LL * HN;
#pragma unroll
    for (int k = 0; k < 64; k += 8) {
        op[(size_t)(l0 + ty + k) * HN + h0 + tx]      = tile[tx][ty + k];
        op[(size_t)(l0 + ty + k) * HN + h0 + tx + 32] = tile[tx + 32][ty + k];
    }
}

// ---------------- launch ----------------
extern "C" void kernel_launch(void* const* d_in, const int* in_sizes, int n_in,
                              void* d_out, int out_size) {
    const float* u   = (const float*)d_in[0];
    const float* Lre = (const float*)d_in[1];
    const float* Lim = (const float*)d_in[2];
    const float* P   = (const float*)d_in[3];
    const float* B   = (const float*)d_in[4];
    const float* C   = (const float*)d_in[5];
    const float* D   = (const float*)d_in[6];
    const float* lst = (const float*)d_in[7];

    const int smem_cv = (4112 + 4368) * sizeof(float2);   // 67840 B
    cudaFuncSetAttribute(k_conv, cudaFuncAttributeMaxDynamicSharedMemorySize, smem_cv);

    k_pre<<<1 + 3 * 2048, NT>>>(u, Lre, Lim, P, B, C, lst);
    k_kernelfft<<<HN, NK>>>();
    k_conv<<<(BT / 2) * HN, NT, smem_cv>>>(D);
    k_transpose_out<<<dim3(LL / 64, HN / 64, BT), dim3(32, 8)>>>((float*)d_out);
}

// round 15
// speedup vs baseline: 1.0378x; 1.0378x over previous
#include <cuda_runtime.h>
#include <math.h>
#include <stdint.h>

#define HN    512
#define NST   64
#define LL    2048
#define LF    4096
#define BT    8
#define NT    256
#define NK    128

// ---------------- scratch ----------------
__device__ float2 g_AT[HN * LL];        // at_roots (h, l)
__device__ float2 g_KF[HN * LF];        // kernel spectrum / 4096
__device__ float  g_UT[BT * HN * LL];   // u transposed (b,h,l)
__device__ float  g_YT[BT * HN * LL];   // y transposed (b,h,l)
__device__ float2 g_TW[2048];           // W_4096^k

// ---------------- helpers ----------------
__device__ __forceinline__ float2 cadd(float2 a, float2 b) { return make_float2(a.x + b.x, a.y + b.y); }
__device__ __forceinline__ float2 csub(float2 a, float2 b) { return make_float2(a.x - b.x, a.y - b.y); }
__device__ __forceinline__ float2 cmulf(float2 a, float2 b) {
    return make_float2(fmaf(a.x, b.x, -(a.y * b.y)), fmaf(a.x, b.y, a.y * b.x));
}

// f32x2 packed math (cauchy)
__device__ __forceinline__ unsigned long long pk2(float a, float b) {
    unsigned long long r; asm("mov.b64 %0, {%1, %2};" : "=l"(r) : "f"(a), "f"(b)); return r;
}
__device__ __forceinline__ void up2(unsigned long long v, float& a, float& b) {
    asm("mov.b64 {%0, %1}, %2;" : "=f"(a), "=f"(b) : "l"(v));
}
__device__ __forceinline__ unsigned long long f2fma(unsigned long long a, unsigned long long b, unsigned long long c) {
    unsigned long long d; asm("fma.rn.f32x2 %0, %1, %2, %3;" : "=l"(d) : "l"(a), "l"(b), "l"(c)); return d;
}
__device__ __forceinline__ unsigned long long f2add(unsigned long long a, unsigned long long b) {
    unsigned long long d; asm("add.rn.f32x2 %0, %1, %2;" : "=l"(d) : "l"(a), "l"(b)); return d;
}
__device__ __forceinline__ unsigned long long f2mul(unsigned long long a, unsigned long long b) {
    unsigned long long d; asm("mul.rn.f32x2 %0, %1, %2;" : "=l"(d) : "l"(a), "l"(b)); return d;
}
// packed negation via sign-bit XOR (ALU pipe, not FMA pipe)
__device__ __forceinline__ unsigned long long f2neg(unsigned long long a) {
    return a ^ 0x8000000080000000ULL;
}
__device__ __forceinline__ float rcpa(float x) {
    float r; asm("rcp.approx.f32 %0, %1;" : "=f"(r) : "f"(x)); return r;
}
__device__ __forceinline__ float hsum(unsigned long long v) {
    float a, b; up2(v, a, b); return a + b;
}

// ---------------- register butterflies ----------------
template <int DIR>
__device__ __forceinline__ void bfly8(const float2 v[8], float2 X[8]) {
    float2 s0 = cadd(v[0], v[4]), d0 = csub(v[0], v[4]);
    float2 s1 = cadd(v[2], v[6]), d1 = csub(v[2], v[6]);
    float2 E0 = cadd(s0, s1), E2 = csub(s0, s1);
    float2 id1 = (DIR < 0) ? make_float2(d1.y, -d1.x) : make_float2(-d1.y, d1.x);
    float2 E1 = cadd(d0, id1), E3 = csub(d0, id1);
    float2 t0 = cadd(v[1], v[5]), u0 = csub(v[1], v[5]);
    float2 t1 = cadd(v[3], v[7]), u1 = csub(v[3], v[7]);
    float2 O0 = cadd(t0, t1), O2 = csub(t0, t1);
    float2 iu1 = (DIR < 0) ? make_float2(u1.y, -u1.x) : make_float2(-u1.y, u1.x);
    float2 O1 = cadd(u0, iu1), O3 = csub(u0, iu1);
    const float c = 0.70710678118654752440f;
    float2 w1O1, w2O2, w3O3;
    if (DIR < 0) {
        w1O1 = make_float2(c * (O1.x + O1.y), c * (O1.y - O1.x));
        w2O2 = make_float2(O2.y, -O2.x);
        w3O3 = make_float2(c * (O3.y - O3.x), -c * (O3.x + O3.y));
    } else {
        w1O1 = make_float2(c * (O1.x - O1.y), c * (O1.x + O1.y));
        w2O2 = make_float2(-O2.y, O2.x);
        w3O3 = make_float2(-c * (O3.x + O3.y), c * (O3.x - O3.y));
    }
    X[0] = cadd(E0, O0);   X[4] = csub(E0, O0);
    X[1] = cadd(E1, w1O1); X[5] = csub(E1, w1O1);
    X[2] = cadd(E2, w2O2); X[6] = csub(E2, w2O2);
    X[3] = cadd(E3, w3O3); X[7] = csub(E3, w3O3);
}

template <int DIR>
__device__ __forceinline__ void fft16(float2 v[16]) {
    const float C1 = 0.9238795325112867f;
    const float S1 = 0.3826834323650898f;
    const float R2 = 0.7071067811865476f;
    const float sg = (DIR < 0) ? -1.0f : 1.0f;
    float2 u[16];
#pragma unroll
    for (int j = 0; j < 4; j++) {
        float2 a = v[j], b = v[j + 4], c = v[j + 8], d = v[j + 12];
        float2 A0 = cadd(a, c), A1 = csub(a, c);
        float2 B0 = cadd(b, d), B1 = csub(b, d);
        float2 iB1 = (DIR < 0) ? make_float2(B1.y, -B1.x) : make_float2(-B1.y, B1.x);
        u[j]      = cadd(A0, B0);
        u[4 + j]  = cadd(A1, iB1);
        u[8 + j]  = csub(A0, B0);
        u[12 + j] = csub(A1, iB1);
    }
    u[5]  = cmulf(u[5],  make_float2(C1,  sg * S1));
    u[6]  = cmulf(u[6],  make_float2(R2,  sg * R2));
    u[7]  = cmulf(u[7],  make_float2(S1,  sg * C1));
    u[9]  = cmulf(u[9],  make_float2(R2,  sg * R2));
    u[10] = (DIR < 0) ? make_float2(u[10].y, -u[10].x) : make_float2(-u[10].y, u[10].x);
    u[11] = cmulf(u[11], make_float2(-R2, sg * R2));
    u[13] = cmulf(u[13], make_float2(S1,  sg * C1));
    u[14] = cmulf(u[14], make_float2(-R2, sg * R2));
    u[15] = cmulf(u[15], make_float2(-C1, -sg * S1));
#pragma unroll
    for (int k = 0; k < 4; k++) {
        float2 a = u[k * 4 + 0], b = u[k * 4 + 1], c = u[k * 4 + 2], d = u[k * 4 + 3];
        float2 A0 = cadd(a, c), A1 = csub(a, c);
        float2 B0 = cadd(b, d), B1 = csub(b, d);
        float2 iB1 = (DIR < 0) ? make_float2(B1.y, -B1.x) : make_float2(-B1.y, B1.x);
        v[k]      = cadd(A0, B0);
        v[k + 4]  = cadd(A1, iB1);
        v[k + 8]  = csub(A0, B0);
        v[k + 12] = csub(A1, iB1);
    }
}

// tree-factored twiddle application: v[k] *= w1^k (conj if CONJ). Depth ~4 vs 14.
template <int CONJ>
__device__ __forceinline__ void twapply(float2 v[16], float2 w1) {
    if (CONJ) w1.y = -w1.y;
    float2 w2  = cmulf(w1, w1);
    float2 w4  = cmulf(w2, w2);
    float2 w8  = cmulf(w4, w4);
    float2 w12 = cmulf(w8, w4);
    float2 w3  = cmulf(w2, w1);
    v[1]  = cmulf(v[1],  w1);
    v[2]  = cmulf(v[2],  w2);
    v[3]  = cmulf(v[3],  w3);
    v[4]  = cmulf(v[4],  w4);
    v[5]  = cmulf(v[5],  cmulf(w4, w1));
    v[6]  = cmulf(v[6],  cmulf(w4, w2));
    v[7]  = cmulf(v[7],  cmulf(w4, w3));
    v[8]  = cmulf(v[8],  w8);
    v[9]  = cmulf(v[9],  cmulf(w8, w1));
    v[10] = cmulf(v[10], cmulf(w8, w2));
    v[11] = cmulf(v[11], cmulf(w8, w3));
    v[12] = cmulf(v[12], w12);
    v[13] = cmulf(v[13], cmulf(w12, w1));
    v[14] = cmulf(v[14], cmulf(w12, w2));
    v[15] = cmulf(v[15], cmulf(w12, w3));
}

// ================= K_pre: fused twiddle + transpose_in(64x64) + cauchy =================

__device__ __forceinline__ void cauchy_body(
        int i, int t, char* smraw,
        const float* __restrict__ Lre, const float* __restrict__ Lim,
        const float* __restrict__ P, const float* __restrict__ B,
        const float* __restrict__ C, const float* __restrict__ logstep) {
    ulonglong2* s_q01 = (ulonglong2*)smraw;          // {-lr pair, -li pair}
    ulonglong2* s_q23 = s_q01 + 32;                  // {w00r, w00i}
    ulonglong2* s_q45 = s_q23 + 32;                  // {w01r, w01i}
    ulonglong2* s_q67 = s_q45 + 32;                  // {w10r, w10i}
    unsigned long long* s_q8 = (unsigned long long*)(s_q67 + 32);  // {w11r}
    int h = i >> 3;
    int bx = i & 7;
    if (t < 32) {
        float lr[2], li[2], w00r[2], w00i[2], w01r[2], w01i[2], w10r[2], w10i[2], w11r[2];
#pragma unroll
        for (int k = 0; k < 2; k++) {
            int idx = h * NST + 2 * t + k;
            lr[k] = fminf(Lre[idx], -1e-4f);
            li[k] = Lim[idx];
            float pr = P[idx * 2], pi = P[idx * 2 + 1];
            float br = B[idx * 2], bi = B[idx * 2 + 1];
            float cr = C[idx * 2], ci = C[idx * 2 + 1];
            w00r[k] = cr * br + ci * bi;  w00i[k] = cr * bi - ci * br;
            w01r[k] = cr * pr + ci * pi;  w01i[k] = cr * pi - ci * pr;
            w10r[k] = pr * br + pi * bi;  w10i[k] = pr * bi - pi * br;
            w11r[k] = pr * pr + pi * pi;
        }
        s_q01[t] = make_ulonglong2(pk2(-lr[0], -lr[1]), pk2(-li[0], -li[1]));
        s_q23[t] = make_ulonglong2(pk2(w00r[0], w00r[1]), pk2(w00i[0], w00i[1]));
        s_q45[t] = make_ulonglong2(pk2(w01r[0], w01r[1]), pk2(w01i[0], w01i[1]));
        s_q67[t] = make_ulonglong2(pk2(w10r[0], w10r[1]), pk2(w10i[0], w10i[1]));
        s_q8[t]  = pk2(w11r[0], w11r[1]);
    }
    __syncthreads();

    int l = bx * NT + t;
    float ts = 2.0f * expf(-logstep[h]);
    float theta = (float)l * (-2.0f * 3.14159265358979323846f / (float)LL);
    float sn, cs;
    sincosf(theta, &sn, &cs);
    float bpr = 1.0f + cs, bpi = sn;
    float amr = 1.0f - cs, ami = -sn;
    float invb = 1.0f / (bpr * bpr + bpi * bpi);
    float gr = ts * (amr * bpr + ami * bpi) * invb;
    float gi = ts * (ami * bpr - amr * bpi) * invb;
    float csr = 2.0f * bpr * invb;
    float csi = -2.0f * bpi * invb;

    unsigned long long gr2 = pk2(gr, gr), gi2 = pk2(gi, gi);
    // folded accumulators: A0=k00r A1=k00i A2=k01r A3=k01i A4=k10r A5=k10i A6=k11r A7=k11i
    unsigned long long A0 = 0, A1 = 0, A2 = 0, A3 = 0, A4 = 0, A5 = 0, A6 = 0, A7 = 0;
#pragma unroll 8
    for (int j = 0; j < 32; j++) {
        ulonglong2 q01 = s_q01[j];
        unsigned long long dr = f2add(gr2, q01.x);
        unsigned long long di = f2add(gi2, q01.y);
        unsigned long long mag = f2fma(dr, dr, f2mul(di, di));
        float m0, m1; up2(mag, m0, m1);
        unsigned long long inv = pk2(rcpa(m0), rcpa(m1));
        unsigned long long rr  = f2mul(dr, inv);
        unsigned long long nri = f2mul(di, inv);   // = -ri
        unsigned long long ri  = f2neg(nri);       // ALU-pipe negate
        ulonglong2 q23 = s_q23[j];
        A0 = f2fma(q23.x, rr, f2fma(q23.y, nri, A0));
        A1 = f2fma(q23.y, rr, f2fma(q23.x, ri,  A1));
        ulonglong2 q45 = s_q45[j];
        A2 = f2fma(q45.x, rr, f2fma(q45.y, nri, A2));
        A3 = f2fma(q45.y, rr, f2fma(q45.x, ri,  A3));
        ulonglong2 q67 = s_q67[j];
        A4 = f2fma(q67.x, rr, f2fma(q67.y, nri, A4));
        A5 = f2fma(q67.y, rr, f2fma(q67.x, ri,  A5));
        unsigned long long q8 = s_q8[j];
        A6 = f2fma(q8, rr, A6);
        A7 = f2fma(q8, ri, A7);
    }
    float k00r = hsum(A0), k00i = hsum(A1);
    float k01r = hsum(A2), k01i = hsum(A3);
    float k10r = hsum(A4), k10i = hsum(A5);
    float k11r = hsum(A6), k11i = hsum(A7);

    float denr = 1.0f + k11r, deni = k11i;
    float invd = 1.0f / (denr * denr + deni * deni);
    float qr = k01r * k10r - k01i * k10i;
    float qi = k01r * k10i + k01i * k10r;
    float fr = (qr * denr + qi * deni) * invd;
    float fi = (qi * denr - qr * deni) * invd;
    float ar_ = k00r - fr, ai_ = k00i - fi;
    g_AT[h * LL + l] = make_float2(csr * ar_ - csi * ai_, csr * ai_ + csi * ar_);
}

// 64x64 transpose-in tile: j in [0, 2048); u (b,l,h) -> g_UT (b,h,l)
__device__ __forceinline__ void transpose_in_body(int j, int t, char* smraw,
                                                  const float* __restrict__ u) {
    float (*tile)[65] = (float (*)[65])smraw;
    int x = j & 7, y = (j >> 3) & 31, b = j >> 8;
    int h0 = x * 64, l0 = y * 64;
    int tx = t & 31, ty = t >> 5;
    const float* up = u + (size_t)b * LL * HN;
#pragma unroll
    for (int k = 0; k < 64; k += 8) {
        tile[ty + k][tx]      = up[(size_t)(l0 + ty + k) * HN + h0 + tx];
        tile[ty + k][tx + 32] = up[(size_t)(l0 + ty + k) * HN + h0 + tx + 32];
    }
    __syncthreads();
    float* o = g_UT + (size_t)b * HN * LL;
#pragma unroll
    for (int k = 0; k < 64; k += 8) {
        o[(size_t)(h0 + ty + k) * LL + l0 + tx]      = tile[tx][ty + k];
        o[(size_t)(h0 + ty + k) * LL + l0 + tx + 32] = tile[tx + 32][ty + k];
    }
}

__global__ void __launch_bounds__(NT, 5) k_pre(
        const float* __restrict__ u,
        const float* __restrict__ Lre, const float* __restrict__ Lim,
        const float* __restrict__ P, const float* __restrict__ B,
        const float* __restrict__ C, const float* __restrict__ logstep) {
    __shared__ __align__(16) char smraw[64 * 65 * 4];
    int t = threadIdx.x;
    int bid = blockIdx.x;
    if (bid == 0) {
#pragma unroll
        for (int k = t; k < 2048; k += NT) {
            double s, c;
            sincospi(-2.0 * (double)k / 4096.0, &s, &c);
            g_TW[k] = make_float2((float)c, (float)s);
        }
        return;
    }
    int i = bid - 1;                 // [0, 6144): 2 cauchy : 1 tin
    int g = i / 3, r = i - 3 * g;    // g in [0, 2048)
    if (r < 2) cauchy_body(2 * g + r, t, smraw, Lre, Lim, P, B, C, logstep);
    else       transpose_in_body(g, t, smraw, u);
}

// ---------------- K2: kernel spectrum, register radix-16 (round-5 proven) ----------------
#define P1 136
#define P2 258

__global__ void __launch_bounds__(NK) k_kernelfft() {
    __shared__ float2 S0[16 * P1];
    __shared__ float2 S1[16 * P1];
    int h = blockIdx.x, t = threadIdx.x;
    const float2* ath = g_AT + (size_t)h * LL;
    float2* kfh = g_KF + (size_t)h * LF;
    const float s2 = 1.0f / 2048.0f, s4 = 1.0f / 4096.0f;
    float2 v[16];

#pragma unroll
    for (int a = 0; a < 16; a++) {
        int n = a * NK + t;
        float2 x = ath[n];
        float2 m = ath[(2048 - n) & 2047];
        float2 ats = make_float2(0.5f * (x.x + m.x), 0.5f * (x.y - m.y));
        v[a] = ats;
        kfh[2 * n] = make_float2(ats.x * s4, ats.y * s4);
    }
    fft16<+1>(v);
    twapply<1>(v, g_TW[2 * t]);
#pragma unroll
    for (int k1 = 0; k1 < 16; k1++) S0[k1 * P1 + t] = v[k1];
    __syncthreads();

    int k1t = t >> 3, t2 = t & 7;
#pragma unroll
    for (int a2 = 0; a2 < 16; a2++) v[a2] = S0[k1t * P1 + a2 * 8 + t2];
    fft16<+1>(v);
    twapply<1>(v, g_TW[32 * t2]);
#pragma unroll
    for (int k2 = 0; k2 < 16; k2++) S1[t2 * P2 + k2 * 16 + k1t] = v[k2];
    __syncthreads();

#pragma unroll
    for (int e = 0; e < 2; e++) {
        int pr = t + NK * e;
        int k1 = pr & 15, k2 = pr >> 4;
        float2 w[8], X[8];
#pragma unroll
        for (int s = 0; s < 8; s++) w[s] = S1[s * P2 + k2 * 16 + k1];
        bfly8<+1>(w, X);
#pragma unroll
        for (int k3 = 0; k3 < 8; k3++) {
            int n = k1 + 16 * k2 + 256 * k3;
            float kr = X[k3].x * s2;
            float2 tw = g_TW[n];
            S0[n] = make_float2(kr * tw.x, kr * tw.y);
        }
    }
    __syncthreads();

#pragma unroll
    for (int a = 0; a < 16; a++) v[a] = S0[a * NK + t];
    fft16<-1>(v);
    twapply<0>(v, g_TW[2 * t]);
#pragma unroll
    for (int k1 = 0; k1 < 16; k1++) S1[k1 * P1 + t] = v[k1];
    __syncthreads();

#pragma unroll
    for (int a2 = 0; a2 < 16; a2++) v[a2] = S1[k1t * P1 + a2 * 8 + t2];
    fft16<-1>(v);
    twapply<0>(v, g_TW[32 * t2]);
#pragma unroll
    for (int k2 = 0; k2 < 16; k2++) S0[t2 * P2 + k2 * 16 + k1t] = v[k2];
    __syncthreads();

#pragma unroll
    for (int e = 0; e < 2; e++) {
        int pr = t + NK * e;
        int k1 = pr & 15, k2 = pr >> 4;
        float2 w[8], X[8];
#pragma unroll
        for (int s = 0; s < 8; s++) w[s] = S0[s * P2 + k2 * 16 + k1];
        bfly8<-1>(w, X);
#pragma unroll
        for (int k3 = 0; k3 < 8; k3++) {
            int j = k1 + 16 * k2 + 256 * k3;
            kfh[2 * j + 1] = make_float2(X[k3].x * s4, X[k3].y * s4);
        }
    }
}

// ================= conv: register radix-16, natural-order (round-8 proven) =================
#define PAD_ROW 257
#define P2C     273

__global__ void __launch_bounds__(NT) k_conv(const float* __restrict__ D) {
    extern __shared__ float2 S[];       // S0[4112] | S1[4368]
    float2* S0 = S;
    float2* S1 = S + 4112;
    int blk = blockIdx.x;
    int h = blk & (HN - 1);
    int bp = blk >> 9;
    int t = threadIdx.x;
    const float* u0 = g_UT + ((size_t)(2 * bp) * HN + h) * LL;
    const float* u1 = g_UT + ((size_t)(2 * bp + 1) * HN + h) * LL;

    int c = t & 15, k1r = t >> 4;
    int sj = 17 * c + k1r;             // slot of G2(k1=t&15, k2=t>>4)
    float2 wA = g_TW[t];               // W4096^t
    float2 wB = g_TW[c << 4];          // W256^c

    float2 v[16];
    // ---- forward ----
#pragma unroll
    for (int a = 0; a < 8; a++) v[a] = make_float2(u0[a * 256 + t], u1[a * 256 + t]);
#pragma unroll
    for (int a = 8; a < 16; a++) v[a] = make_float2(0.0f, 0.0f);
    fft16<-1>(v);
    twapply<0>(v, wA);
#pragma unroll
    for (int k1 = 0; k1 < 16; k1++) S0[k1 * PAD_ROW + t] = v[k1];
    __syncthreads();
#pragma unroll
    for (int b = 0; b < 16; b++) v[b] = S0[k1r * PAD_ROW + b * 16 + c];
    fft16<-1>(v);
    twapply<0>(v, wB);
#pragma unroll
    for (int k2 = 0; k2 < 16; k2++) S1[c * P2C + 17 * k1r + k2] = v[k2];
    __syncthreads();
#pragma unroll
    for (int cc = 0; cc < 16; cc++) v[cc] = S1[cc * P2C + sj];
    fft16<-1>(v);
    // thread t holds X[t + 256*k3] — natural order

    // ---- pointwise * KF/4096 (coalesced) ----
    const float2* kf = g_KF + (size_t)h * LF;
#pragma unroll
    for (int k3 = 0; k3 < 16; k3++) v[k3] = cmulf(v[k3], __ldg(&kf[(k3 << 8) + t]));

    // ---- inverse: mirror of forward, conj twiddles ----
    fft16<+1>(v);
    twapply<1>(v, wA);
#pragma unroll
    for (int j1 = 0; j1 < 16; j1++) S0[j1 * PAD_ROW + t] = v[j1];
    __syncthreads();
#pragma unroll
    for (int b = 0; b < 16; b++) v[b] = S0[k1r * PAD_ROW + b * 16 + c];
    fft16<+1>(v);
    twapply<1>(v, wB);
#pragma unroll
    for (int j2 = 0; j2 < 16; j2++) S1[c * P2C + 17 * k1r + j2] = v[j2];
    __syncthreads();
#pragma unroll
    for (int cc = 0; cc < 16; cc++) v[cc] = S1[cc * P2C + sj];
    fft16<+1>(v);
    float dv = D[h];
    float* y0 = g_YT + ((size_t)(2 * bp) * HN + h) * LL;
    float* y1 = g_YT + ((size_t)(2 * bp + 1) * HN + h) * LL;
#pragma unroll
    for (int j3 = 0; j3 < 8; j3++) {
        int n = t + (j3 << 8);
        y0[n] = fmaf(dv, u0[n], v[j3].x);
        y1[n] = fmaf(dv, u1[n], v[j3].y);
    }
}

// ---------------- K5: transpose y (b,h,l) -> out (b,l,h), 64x64 tiles ----------------
__global__ void k_transpose_out(float* __restrict__ out) {
    __shared__ float tile[64][65];
    int b = blockIdx.z;
    int l0 = blockIdx.x * 64, h0 = blockIdx.y * 64;
    int tx = threadIdx.x, ty = threadIdx.y;
    const float* yp = g_YT + (size_t)b * HN * LL;
#pragma unroll
    for (int k = 0; k < 64; k += 8) {
        tile[ty + k][tx]      = yp[(size_t)(h0 + ty + k) * LL + l0 + tx];
        tile[ty + k][tx + 32] = yp[(size_t)(h0 + ty + k) * LL + l0 + tx + 32];
    }
    __syncthreads();
    float* op = out + (size_t)b * LL * HN;
#pragma unroll
    for (int k = 0; k < 64; k += 8) {
        op[(size_t)(l0 + ty + k) * HN + h0 + tx]      = tile[tx][ty + k];
        op[(size_t)(l0 + ty + k) * HN + h0 + tx + 32] = tile[tx + 32][ty + k];
    }
}

// ---------------- launch ----------------
extern "C" void kernel_launch(void* const* d_in, const int* in_sizes, int n_in,
                              void* d_out, int out_size) {
    const float* u   = (const float*)d_in[0];
    const float* Lre = (const float*)d_in[1];
    const float* Lim = (const float*)d_in[2];
    const float* P   = (const float*)d_in[3];
    const float* B   = (const float*)d_in[4];
    const float* C   = (const float*)d_in[5];
    const float* D   = (const float*)d_in[6];
    const float* lst = (const float*)d_in[7];

    const int smem_cv = (4112 + 4368) * sizeof(float2);   // 67840 B
    cudaFuncSetAttribute(k_conv, cudaFuncAttributeMaxDynamicSharedMemorySize, smem_cv);

    k_pre<<<1 + 3 * 2048, NT>>>(u, Lre, Lim, P, B, C, lst);
    k_kernelfft<<<HN, NK>>>();
    k_conv<<<(BT / 2) * HN, NT, smem_cv>>>(D);
    k_transpose_out<<<dim3(LL / 64, HN / 64, BT), dim3(32, 8)>>>((float*)d_out);
}

// round 17
// speedup vs baseline: 1.0440x; 1.0060x over previous
#include <cuda_runtime.h>
#include <math.h>
#include <stdint.h>

#define HN    512
#define NST   64
#define LL    2048
#define LF    4096
#define BT    8
#define NT    256
#define NK    128

// ---------------- scratch ----------------
__device__ float2 g_AT[HN * LL];        // at_roots (h, l)
__device__ float2 g_KF[HN * LF];        // kernel spectrum / 4096
__device__ float  g_UT[BT * HN * LL];   // u transposed (b,h,l)
__device__ float  g_YT[BT * HN * LL];   // y transposed (b,h,l)
__device__ float2 g_TW[2048];           // W_4096^k

// ---------------- helpers ----------------
__device__ __forceinline__ float2 cadd(float2 a, float2 b) { return make_float2(a.x + b.x, a.y + b.y); }
__device__ __forceinline__ float2 csub(float2 a, float2 b) { return make_float2(a.x - b.x, a.y - b.y); }
__device__ __forceinline__ float2 cmulf(float2 a, float2 b) {
    return make_float2(fmaf(a.x, b.x, -(a.y * b.y)), fmaf(a.x, b.y, a.y * b.x));
}

// f32x2 packed math (cauchy)
__device__ __forceinline__ unsigned long long pk2(float a, float b) {
    unsigned long long r; asm("mov.b64 %0, {%1, %2};" : "=l"(r) : "f"(a), "f"(b)); return r;
}
__device__ __forceinline__ void up2(unsigned long long v, float& a, float& b) {
    asm("mov.b64 {%0, %1}, %2;" : "=f"(a), "=f"(b) : "l"(v));
}
__device__ __forceinline__ unsigned long long f2fma(unsigned long long a, unsigned long long b, unsigned long long c) {
    unsigned long long d; asm("fma.rn.f32x2 %0, %1, %2, %3;" : "=l"(d) : "l"(a), "l"(b), "l"(c)); return d;
}
__device__ __forceinline__ unsigned long long f2add(unsigned long long a, unsigned long long b) {
    unsigned long long d; asm("add.rn.f32x2 %0, %1, %2;" : "=l"(d) : "l"(a), "l"(b)); return d;
}
__device__ __forceinline__ unsigned long long f2mul(unsigned long long a, unsigned long long b) {
    unsigned long long d; asm("mul.rn.f32x2 %0, %1, %2;" : "=l"(d) : "l"(a), "l"(b)); return d;
}
__device__ __forceinline__ unsigned long long f2neg(unsigned long long a) {
    return a ^ 0x8000000080000000ULL;
}
__device__ __forceinline__ float rcpa(float x) {
    float r; asm("rcp.approx.f32 %0, %1;" : "=f"(r) : "f"(x)); return r;
}
__device__ __forceinline__ float hsum(unsigned long long v) {
    float a, b; up2(v, a, b); return a + b;
}

// ---------------- register butterflies ----------------
template <int DIR>
__device__ __forceinline__ void bfly8(const float2 v[8], float2 X[8]) {
    float2 s0 = cadd(v[0], v[4]), d0 = csub(v[0], v[4]);
    float2 s1 = cadd(v[2], v[6]), d1 = csub(v[2], v[6]);
    float2 E0 = cadd(s0, s1), E2 = csub(s0, s1);
    float2 id1 = (DIR < 0) ? make_float2(d1.y, -d1.x) : make_float2(-d1.y, d1.x);
    float2 E1 = cadd(d0, id1), E3 = csub(d0, id1);
    float2 t0 = cadd(v[1], v[5]), u0 = csub(v[1], v[5]);
    float2 t1 = cadd(v[3], v[7]), u1 = csub(v[3], v[7]);
    float2 O0 = cadd(t0, t1), O2 = csub(t0, t1);
    float2 iu1 = (DIR < 0) ? make_float2(u1.y, -u1.x) : make_float2(-u1.y, u1.x);
    float2 O1 = cadd(u0, iu1), O3 = csub(u0, iu1);
    const float c = 0.70710678118654752440f;
    float2 w1O1, w2O2, w3O3;
    if (DIR < 0) {
        w1O1 = make_float2(c * (O1.x + O1.y), c * (O1.y - O1.x));
        w2O2 = make_float2(O2.y, -O2.x);
        w3O3 = make_float2(c * (O3.y - O3.x), -c * (O3.x + O3.y));
    } else {
        w1O1 = make_float2(c * (O1.x - O1.y), c * (O1.x + O1.y));
        w2O2 = make_float2(-O2.y, O2.x);
        w3O3 = make_float2(-c * (O3.x + O3.y), c * (O3.x - O3.y));
    }
    X[0] = cadd(E0, O0);   X[4] = csub(E0, O0);
    X[1] = cadd(E1, w1O1); X[5] = csub(E1, w1O1);
    X[2] = cadd(E2, w2O2); X[6] = csub(E2, w2O2);
    X[3] = cadd(E3, w3O3); X[7] = csub(E3, w3O3);
}

// common tail of the 16-pt FFT
template <int DIR>
__device__ __forceinline__ void fft16_tail(float2 u[16], float2 v[16]) {
    const float C1 = 0.9238795325112867f;
    const float S1 = 0.3826834323650898f;
    const float R2 = 0.7071067811865476f;
    const float sg = (DIR < 0) ? -1.0f : 1.0f;
    u[5]  = cmulf(u[5],  make_float2(C1,  sg * S1));
    u[6]  = cmulf(u[6],  make_float2(R2,  sg * R2));
    u[7]  = cmulf(u[7],  make_float2(S1,  sg * C1));
    u[9]  = cmulf(u[9],  make_float2(R2,  sg * R2));
    u[10] = (DIR < 0) ? make_float2(u[10].y, -u[10].x) : make_float2(-u[10].y, u[10].x);
    u[11] = cmulf(u[11], make_float2(-R2, sg * R2));
    u[13] = cmulf(u[13], make_float2(S1,  sg * C1));
    u[14] = cmulf(u[14], make_float2(-R2, sg * R2));
    u[15] = cmulf(u[15], make_float2(-C1, -sg * S1));
#pragma unroll
    for (int k = 0; k < 4; k++) {
        float2 a = u[k * 4 + 0], b = u[k * 4 + 1], c = u[k * 4 + 2], d = u[k * 4 + 3];
        float2 A0 = cadd(a, c), A1 = csub(a, c);
        float2 B0 = cadd(b, d), B1 = csub(b, d);
        float2 iB1 = (DIR < 0) ? make_float2(B1.y, -B1.x) : make_float2(-B1.y, B1.x);
        v[k]      = cadd(A0, B0);
        v[k + 4]  = cadd(A1, iB1);
        v[k + 8]  = csub(A0, B0);
        v[k + 12] = csub(A1, iB1);
    }
}

template <int DIR>
__device__ __forceinline__ void fft16(float2 v[16]) {
    float2 u[16];
#pragma unroll
    for (int j = 0; j < 4; j++) {
        float2 a = v[j], b = v[j + 4], c = v[j + 8], d = v[j + 12];
        float2 A0 = cadd(a, c), A1 = csub(a, c);
        float2 B0 = cadd(b, d), B1 = csub(b, d);
        float2 iB1 = (DIR < 0) ? make_float2(B1.y, -B1.x) : make_float2(-B1.y, B1.x);
        u[j]      = cadd(A0, B0);
        u[4 + j]  = cadd(A1, iB1);
        u[8 + j]  = csub(A0, B0);
        u[12 + j] = csub(A1, iB1);
    }
    fft16_tail<DIR>(u, v);
}

// 16-pt FFT where v[8..15] are implicitly ZERO
template <int DIR>
__device__ __forceinline__ void fft16h(float2 v[16]) {
    float2 u[16];
#pragma unroll
    for (int j = 0; j < 4; j++) {
        float2 a = v[j], b = v[j + 4];
        float2 ib = (DIR < 0) ? make_float2(b.y, -b.x) : make_float2(-b.y, b.x);
        u[j]      = cadd(a, b);
        u[4 + j]  = cadd(a, ib);
        u[8 + j]  = csub(a, b);
        u[12 + j] = csub(a, ib);
    }
    fft16_tail<DIR>(u, v);
}

// tree-factored twiddle application: v[k] *= w1^k (conj if CONJ)
template <int CONJ>
__device__ __forceinline__ void twapply(float2 v[16], float2 w1) {
    if (CONJ) w1.y = -w1.y;
    float2 w2  = cmulf(w1, w1);
    float2 w4  = cmulf(w2, w2);
    float2 w8  = cmulf(w4, w4);
    float2 w12 = cmulf(w8, w4);
    float2 w3  = cmulf(w2, w1);
    v[1]  = cmulf(v[1],  w1);
    v[2]  = cmulf(v[2],  w2);
    v[3]  = cmulf(v[3],  w3);
    v[4]  = cmulf(v[4],  w4);
    v[5]  = cmulf(v[5],  cmulf(w4, w1));
    v[6]  = cmulf(v[6],  cmulf(w4, w2));
    v[7]  = cmulf(v[7],  cmulf(w4, w3));
    v[8]  = cmulf(v[8],  w8);
    v[9]  = cmulf(v[9],  cmulf(w8, w1));
    v[10] = cmulf(v[10], cmulf(w8, w2));
    v[11] = cmulf(v[11], cmulf(w8, w3));
    v[12] = cmulf(v[12], w12);
    v[13] = cmulf(v[13], cmulf(w12, w1));
    v[14] = cmulf(v[14], cmulf(w12, w2));
    v[15] = cmulf(v[15], cmulf(w12, w3));
}

// ================= K_pre: fused twiddle + transpose_in(64x64) + cauchy =================

__device__ __forceinline__ void cauchy_body(
        int i, int t, char* smraw,
        const float* __restrict__ Lre, const float* __restrict__ Lim,
        const float* __restrict__ P, const float* __restrict__ B,
        const float* __restrict__ C, const float* __restrict__ logstep) {
    ulonglong2* s_q01 = (ulonglong2*)smraw;
    ulonglong2* s_q23 = s_q01 + 32;
    ulonglong2* s_q45 = s_q23 + 32;
    ulonglong2* s_q67 = s_q45 + 32;
    unsigned long long* s_q8 = (unsigned long long*)(s_q67 + 32);
    int h = i >> 3;
    int bx = i & 7;
    if (t < 32) {
        float lr[2], li[2], w00r[2], w00i[2], w01r[2], w01i[2], w10r[2], w10i[2], w11r[2];
#pragma unroll
        for (int k = 0; k < 2; k++) {
            int idx = h * NST + 2 * t + k;
            lr[k] = fminf(Lre[idx], -1e-4f);
            li[k] = Lim[idx];
            float pr = P[idx * 2], pi = P[idx * 2 + 1];
            float br = B[idx * 2], bi = B[idx * 2 + 1];
            float cr = C[idx * 2], ci = C[idx * 2 + 1];
            w00r[k] = cr * br + ci * bi;  w00i[k] = cr * bi - ci * br;
            w01r[k] = cr * pr + ci * pi;  w01i[k] = cr * pi - ci * pr;
            w10r[k] = pr * br + pi * bi;  w10i[k] = pr * bi - pi * br;
            w11r[k] = pr * pr + pi * pi;
        }
        s_q01[t] = make_ulonglong2(pk2(-lr[0], -lr[1]), pk2(-li[0], -li[1]));
        s_q23[t] = make_ulonglong2(pk2(w00r[0], w00r[1]), pk2(w00i[0], w00i[1]));
        s_q45[t] = make_ulonglong2(pk2(w01r[0], w01r[1]), pk2(w01i[0], w01i[1]));
        s_q67[t] = make_ulonglong2(pk2(w10r[0], w10r[1]), pk2(w10i[0], w10i[1]));
        s_q8[t]  = pk2(w11r[0], w11r[1]);
    }
    __syncthreads();

    int l = bx * NT + t;
    float ts = 2.0f * expf(-logstep[h]);
    // Omega(l) = -exp(i*theta_c), theta_c = -(2*pi/L)*(l-1024) in (-pi, pi]
    float theta_c = (float)(l - 1024) * (-2.0f * 3.14159265358979323846f / (float)LL);
    float snc, csc_;
    __sincosf(theta_c, &snc, &csc_);
    float cs = -csc_, sn = -snc;
    if (l == 1024) { cs = -1.0f; sn = 1.1920929e-7f; }   // singular bin: benign self-cancelling config
    float bpr = 1.0f + cs, bpi = sn;
    float amr = 1.0f - cs, ami = -sn;
    float invb = 1.0f / (bpr * bpr + bpi * bpi);
    float gr = ts * (amr * bpr + ami * bpi) * invb;
    float gi = ts * (ami * bpr - amr * bpi) * invb;
    float csr = 2.0f * bpr * invb;
    float csi = -2.0f * bpi * invb;

    unsigned long long gr2 = pk2(gr, gr), gi2 = pk2(gi, gi);
    unsigned long long A0 = 0, A1 = 0, A2 = 0, A3 = 0, A4 = 0, A5 = 0, A6 = 0, A7 = 0;
#pragma unroll 8
    for (int j = 0; j < 32; j++) {
        ulonglong2 q01 = s_q01[j];
        unsigned long long dr = f2add(gr2, q01.x);
        unsigned long long di = f2add(gi2, q01.y);
        unsigned long long mag = f2fma(dr, dr, f2mul(di, di));
        float m0, m1; up2(mag, m0, m1);
        unsigned long long inv = pk2(rcpa(m0), rcpa(m1));
        unsigned long long rr  = f2mul(dr, inv);
        unsigned long long nri = f2mul(di, inv);
        unsigned long long ri  = f2neg(nri);
        ulonglong2 q23 = s_q23[j];
        A0 = f2fma(q23.x, rr, f2fma(q23.y, nri, A0));
        A1 = f2fma(q23.y, rr, f2fma(q23.x, ri,  A1));
        ulonglong2 q45 = s_q45[j];
        A2 = f2fma(q45.x, rr, f2fma(q45.y, nri, A2));
        A3 = f2fma(q45.y, rr, f2fma(q45.x, ri,  A3));
        ulonglong2 q67 = s_q67[j];
        A4 = f2fma(q67.x, rr, f2fma(q67.y, nri, A4));
        A5 = f2fma(q67.y, rr, f2fma(q67.x, ri,  A5));
        unsigned long long q8 = s_q8[j];
        A6 = f2fma(q8, rr, A6);
        A7 = f2fma(q8, ri, A7);
    }
    float k00r = hsum(A0), k00i = hsum(A1);
    float k01r = hsum(A2), k01i = hsum(A3);
    float k10r = hsum(A4), k10i = hsum(A5);
    float k11r = hsum(A6), k11i = hsum(A7);

    float denr = 1.0f + k11r, deni = k11i;
    float invd = 1.0f / (denr * denr + deni * deni);
    float qr = k01r * k10r - k01i * k10i;
    float qi = k01r * k10i + k01i * k10r;
    float fr = (qr * denr + qi * deni) * invd;
    float fi = (qi * denr - qr * deni) * invd;
    float ar_ = k00r - fr, ai_ = k00i - fi;
    g_AT[h * LL + l] = make_float2(csr * ar_ - csi * ai_, csr * ai_ + csi * ar_);
}

// 64x64 transpose-in tile: j in [0, 2048); u (b,l,h) -> g_UT (b,h,l)
__device__ __forceinline__ void transpose_in_body(int j, int t, char* smraw,
                                                  const float* __restrict__ u) {
    float (*tile)[65] = (float (*)[65])smraw;
    int x = j & 7, y = (j >> 3) & 31, b = j >> 8;
    int h0 = x * 64, l0 = y * 64;
    int tx = t & 31, ty = t >> 5;
    const float* up = u + (size_t)b * LL * HN;
#pragma unroll
    for (int k = 0; k < 64; k += 8) {
        tile[ty + k][tx]      = up[(size_t)(l0 + ty + k) * HN + h0 + tx];
        tile[ty + k][tx + 32] = up[(size_t)(l0 + ty + k) * HN + h0 + tx + 32];
    }
    __syncthreads();
    float* o = g_UT + (size_t)b * HN * LL;
#pragma unroll
    for (int k = 0; k < 64; k += 8) {
        o[(size_t)(h0 + ty + k) * LL + l0 + tx]      = tile[tx][ty + k];
        o[(size_t)(h0 + ty + k) * LL + l0 + tx + 32] = tile[tx + 32][ty + k];
    }
}

__global__ void __launch_bounds__(NT, 5) k_pre(
        const float* __restrict__ u,
        const float* __restrict__ Lre, const float* __restrict__ Lim,
        const float* __restrict__ P, const float* __restrict__ B,
        const float* __restrict__ C, const float* __restrict__ logstep) {
    __shared__ __align__(16) char smraw[64 * 65 * 4];
    int t = threadIdx.x;
    int bid = blockIdx.x;
    if (bid == 0) {
#pragma unroll
        for (int k = t; k < 2048; k += NT) {
            double s, c;
            sincospi(-2.0 * (double)k / 4096.0, &s, &c);
            g_TW[k] = make_float2((float)c, (float)s);
        }
        return;
    }
    int i = bid - 1;                 // [0, 6144): 2 cauchy : 1 tin
    int g = i / 3, r = i - 3 * g;
    if (r < 2) cauchy_body(2 * g + r, t, smraw, Lre, Lim, P, B, C, logstep);
    else       transpose_in_body(g, t, smraw, u);
}

// ---------------- K2: kernel spectrum, register radix-16 (round-5 proven) ----------------
#define P1 136
#define P2 258

__global__ void __launch_bounds__(NK) k_kernelfft() {
    __shared__ float2 S0[16 * P1];
    __shared__ float2 S1[16 * P1];
    int h = blockIdx.x, t = threadIdx.x;
    const float2* ath = g_AT + (size_t)h * LL;
    float2* kfh = g_KF + (size_t)h * LF;
    const float s2 = 1.0f / 2048.0f, s4 = 1.0f / 4096.0f;
    float2 v[16];

#pragma unroll
    for (int a = 0; a < 16; a++) {
        int n = a * NK + t;
        float2 x = ath[n];
        float2 m = ath[(2048 - n) & 2047];
        float2 ats = make_float2(0.5f * (x.x + m.x), 0.5f * (x.y - m.y));
        v[a] = ats;
        kfh[2 * n] = make_float2(ats.x * s4, ats.y * s4);
    }
    fft16<+1>(v);
    twapply<1>(v, g_TW[2 * t]);
#pragma unroll
    for (int k1 = 0; k1 < 16; k1++) S0[k1 * P1 + t] = v[k1];
    __syncthreads();

    int k1t = t >> 3, t2 = t & 7;
#pragma unroll
    for (int a2 = 0; a2 < 16; a2++) v[a2] = S0[k1t * P1 + a2 * 8 + t2];
    fft16<+1>(v);
    twapply<1>(v, g_TW[32 * t2]);
#pragma unroll
    for (int k2 = 0; k2 < 16; k2++) S1[t2 * P2 + k2 * 16 + k1t] = v[k2];
    __syncthreads();

#pragma unroll
    for (int e = 0; e < 2; e++) {
        int pr = t + NK * e;
        int k1 = pr & 15, k2 = pr >> 4;
        float2 w[8], X[8];
#pragma unroll
        for (int s = 0; s < 8; s++) w[s] = S1[s * P2 + k2 * 16 + k1];
        bfly8<+1>(w, X);
#pragma unroll
        for (int k3 = 0; k3 < 8; k3++) {
            int n = k1 + 16 * k2 + 256 * k3;
            float kr = X[k3].x * s2;
            float2 tw = g_TW[n];
            S0[n] = make_float2(kr * tw.x, kr * tw.y);
        }
    }
    __syncthreads();

#pragma unroll
    for (int a = 0; a < 16; a++) v[a] = S0[a * NK + t];
    fft16<-1>(v);
    twapply<0>(v, g_TW[2 * t]);
#pragma unroll
    for (int k1 = 0; k1 < 16; k1++) S1[k1 * P1 + t] = v[k1];
    __syncthreads();

#pragma unroll
    for (int a2 = 0; a2 < 16; a2++) v[a2] = S1[k1t * P1 + a2 * 8 + t2];
    fft16<-1>(v);
    twapply<0>(v, g_TW[32 * t2]);
#pragma unroll
    for (int k2 = 0; k2 < 16; k2++) S0[t2 * P2 + k2 * 16 + k1t] = v[k2];
    __syncthreads();

#pragma unroll
    for (int e = 0; e < 2; e++) {
        int pr = t + NK * e;
        int k1 = pr & 15, k2 = pr >> 4;
        float2 w[8], X[8];
#pragma unroll
        for (int s = 0; s < 8; s++) w[s] = S0[s * P2 + k2 * 16 + k1];
        bfly8<-1>(w, X);
#pragma unroll
        for (int k3 = 0; k3 < 8; k3++) {
            int j = k1 + 16 * k2 + 256 * k3;
            kfh[2 * j + 1] = make_float2(X[k3].x * s4, X[k3].y * s4);
        }
    }
}

// ================= conv: register radix-16, natural-order (round-8 proven) =================
#define PAD_ROW 257
#define P2C     273

__global__ void __launch_bounds__(NT) k_conv(const float* __restrict__ D) {
    extern __shared__ float2 S[];       // S0[4112] | S1[4368]
    float2* S0 = S;
    float2* S1 = S + 4112;
    int blk = blockIdx.x;
    int h = blk & (HN - 1);
    int bp = blk >> 9;
    int t = threadIdx.x;
    const float* u0 = g_UT + ((size_t)(2 * bp) * HN + h) * LL;
    const float* u1 = g_UT + ((size_t)(2 * bp + 1) * HN + h) * LL;

    int c = t & 15, k1r = t >> 4;
    int sj = 17 * c + k1r;
    float2 wA = g_TW[t];
    float2 wB = g_TW[c << 4];

    float2 v[16];
    // ---- forward (upper half zero -> fft16h) ----
#pragma unroll
    for (int a = 0; a < 8; a++) v[a] = make_float2(u0[a * 256 + t], u1[a * 256 + t]);
    fft16h<-1>(v);
    twapply<0>(v, wA);
#pragma unroll
    for (int k1 = 0; k1 < 16; k1++) S0[k1 * PAD_ROW + t] = v[k1];
    __syncthreads();
#pragma unroll
    for (int b = 0; b < 16; b++) v[b] = S0[k1r * PAD_ROW + b * 16 + c];
    fft16<-1>(v);
    twapply<0>(v, wB);
#pragma unroll
    for (int k2 = 0; k2 < 16; k2++) S1[c * P2C + 17 * k1r + k2] = v[k2];
    __syncthreads();
#pragma unroll
    for (int cc = 0; cc < 16; cc++) v[cc] = S1[cc * P2C + sj];
    fft16<-1>(v);
    // thread t holds X[t + 256*k3] — natural order

    // ---- pointwise * KF/4096 (coalesced) ----
    const float2* kf = g_KF + (size_t)h * LF;
#pragma unroll
    for (int k3 = 0; k3 < 16; k3++) v[k3] = cmulf(v[k3], __ldg(&kf[(k3 << 8) + t]));

    // ---- inverse: mirror of forward, conj twiddles ----
    fft16<+1>(v);
    twapply<1>(v, wA);
#pragma unroll
    for (int j1 = 0; j1 < 16; j1++) S0[j1 * PAD_ROW + t] = v[j1];
    __syncthreads();
#pragma unroll
    for (int b = 0; b < 16; b++) v[b] = S0[k1r * PAD_ROW + b * 16 + c];
    fft16<+1>(v);
    twapply<1>(v, wB);
#pragma unroll
    for (int j2 = 0; j2 < 16; j2++) S1[c * P2C + 17 * k1r + j2] = v[j2];
    __syncthreads();
#pragma unroll
    for (int cc = 0; cc < 16; cc++) v[cc] = S1[cc * P2C + sj];
    fft16<+1>(v);
    float dv = D[h];
    float* y0 = g_YT + ((size_t)(2 * bp) * HN + h) * LL;
    float* y1 = g_YT + ((size_t)(2 * bp + 1) * HN + h) * LL;
#pragma unroll
    for (int j3 = 0; j3 < 8; j3++) {
        int n = t + (j3 << 8);
        y0[n] = fmaf(dv, u0[n], v[j3].x);
        y1[n] = fmaf(dv, u1[n], v[j3].y);
    }
}

// ---------------- K5: transpose y (b,h,l) -> out (b,l,h), 64x64 tiles ----------------
__global__ void k_transpose_out(float* __restrict__ out) {
    __shared__ float tile[64][65];
    int b = blockIdx.z;
    int l0 = blockIdx.x * 64, h0 = blockIdx.y * 64;
    int tx = threadIdx.x, ty = threadIdx.y;
    const float* yp = g_YT + (size_t)b * HN * LL;
#pragma unroll
    for (int k = 0; k < 64; k += 8) {
        tile[ty + k][tx]      = yp[(size_t)(h0 + ty + k) * LL + l0 + tx];
        tile[ty + k][tx + 32] = yp[(size_t)(h0 + ty + k) * LL + l0 + tx + 32];
    }
    __syncthreads();
    float* op = out + (size_t)b * LL * HN;
#pragma unroll
    for (int k = 0; k < 64; k += 8) {
        op[(size_t)(l0 + ty + k) * HN + h0 + tx]      = tile[tx][ty + k];
        op[(size_t)(l0 + ty + k) * HN + h0 + tx + 32] = tile[tx + 32][ty + k];
    }
}

// ---------------- launch ----------------
extern "C" void kernel_launch(void* const* d_in, const int* in_sizes, int n_in,
                              void* d_out, int out_size) {
    const float* u   = (const float*)d_in[0];
    const float* Lre = (const float*)d_in[1];
    const float* Lim = (const float*)d_in[2];
    const float* P   = (const float*)d_in[3];
    const float* B   = (const float*)d_in[4];
    const float* C   = (const float*)d_in[5];
    const float* D   = (const float*)d_in[6];
    const float* lst = (const float*)d_in[7];

    const int smem_cv = (4112 + 4368) * sizeof(float2);   // 67840 B
    cudaFuncSetAttribute(k_conv, cudaFuncAttributeMaxDynamicSharedMemorySize, smem_cv);

    k_pre<<<1 + 3 * 2048, NT>>>(u, Lre, Lim, P, B, C, lst);
    k_kernelfft<<<HN, NK>>>();
    k_conv<<<(BT / 2) * HN, NT, smem_cv>>>(D);
    k_transpose_out<<<dim3(LL / 64, HN / 64, BT), dim3(32, 8)>>>((float*)d_out);
}